// round 13
// baseline (speedup 1.0000x reference)
#include <cuda_runtime.h>
#include <cuda_fp16.h>

#define NN 50000
#define NE 1600000
#define PAD 128

// ---------------- scratch (device globals; zero-initialized at load) ----------
__device__ __align__(16) __half g_xh[NN * 128];
__device__ float g_al[NN * 8];
__device__ float g_ar[NN * 8];
__device__ int   g_cnt[NN];          // zeroed at load; reset at TAIL of k_agg
__device__ __align__(16) int2 g_cs[NN * PAD];

// ---------------- fused: tf32 GEMM (+al/ar epilogue)  ||  edge scatter ---------
// Roles INTERLEAVED by blockIdx (idx%3==0 -> GEMM, else scatter) so each
// scheduling wave mixes smem-heavy GEMM blocks with smem-free scatter blocks.
#define SF 132
#define SW 136
#define GEMM_SMEM_BYTES ((128 * SF + 128 * SW) * 4)

__device__ __forceinline__ unsigned f2tf32(float f) {
    unsigned u;
    asm("cvt.rna.tf32.f32 %0, %1;" : "=r"(u) : "f"(f));
    return u;
}

__global__ void __launch_bounds__(256) k_fused(
    const float* __restrict__ feat, const float* __restrict__ Wlin,
    const float* __restrict__ Wres, const float* __restrict__ attl,
    const float* __restrict__ attr, float* __restrict__ dres,
    const int* __restrict__ esrc, const int* __restrict__ edst,
    const float* __restrict__ ew, int n, int e, int gb) {

    int idx = blockIdx.x;
    int gsel = idx / 3;
    bool is_gemm = (idx % 3 == 0) && (gsel < gb);

    if (!is_gemm) {
        // ================= scatter role =================
        // sid = idx minus number of gemm-marked blocks in [0, idx)
        int sbid = (idx % 3 == 0) ? (idx - gb) /*overflow gemm slots -> tail ids*/
                                  : (idx - (idx + 2) / 3);
        int i0 = (sbid * 256 + threadIdx.x) * 4;
        if (i0 + 4 <= e) {
            int4   s4 = *(const int4*)&esrc[i0];
            int4   d4 = *(const int4*)&edst[i0];
            float4 w4 = *(const float4*)&ew[i0];
            int p0 = atomicAdd(&g_cnt[d4.x], 1);
            int p1 = atomicAdd(&g_cnt[d4.y], 1);
            int p2 = atomicAdd(&g_cnt[d4.z], 1);
            int p3 = atomicAdd(&g_cnt[d4.w], 1);
            p0 = min(p0, PAD - 1); p1 = min(p1, PAD - 1);
            p2 = min(p2, PAD - 1); p3 = min(p3, PAD - 1);
            g_cs[d4.x * PAD + p0] = make_int2(s4.x, __float_as_int(w4.x));
            g_cs[d4.y * PAD + p1] = make_int2(s4.y, __float_as_int(w4.y));
            g_cs[d4.z * PAD + p2] = make_int2(s4.z, __float_as_int(w4.z));
            g_cs[d4.w * PAD + p3] = make_int2(s4.w, __float_as_int(w4.w));
        } else {
            for (int i = i0; i < e && i >= 0; i++) {
                int d = edst[i];
                int p = min(atomicAdd(&g_cnt[d], 1), PAD - 1);
                g_cs[d * PAD + p] = make_int2(esrc[i], __float_as_int(ew[i]));
            }
        }
        return;
    }

    // ================= GEMM role =================
    int bx = gsel >> 1;
    int by = gsel & 1;                // 0 -> x/g_xh (+al/ar), 1 -> residual
    extern __shared__ float sm[];
    float* sF = sm;
    float* sW = sm + 128 * SF;
    int tid = threadIdx.x;
    const float* W = by ? Wres : Wlin;
    int node0 = bx * 128;

#pragma unroll
    for (int t = 0; t < 16; t++) {
        int i = tid + t * 256;
        int r = i >> 5;
        int c4 = i & 31;
        float4 v = ((const float4*)W)[i];
        uint4 u = make_uint4(f2tf32(v.x), f2tf32(v.y), f2tf32(v.z), f2tf32(v.w));
        *(uint4*)&sW[r * SW + c4 * 4] = u;
    }
#pragma unroll
    for (int t = 0; t < 16; t++) {
        int i = tid + t * 256;
        int r = i >> 5;
        int c4 = i & 31;
        int gn = node0 + r;
        float4 v = make_float4(0.f, 0.f, 0.f, 0.f);
        if (gn < n) v = ((const float4*)feat)[gn * 32 + c4];
        uint4 u = make_uint4(f2tf32(v.x), f2tf32(v.y), f2tf32(v.z), f2tf32(v.w));
        *(uint4*)&sF[r * SF + c4 * 4] = u;
    }
    __syncthreads();

    int w = tid >> 5, lane = tid & 31;
    int wm = (w >> 2) * 64;
    int wn = (w & 3) * 32;
    int gid = lane >> 2, tig = lane & 3;

    float c[4][4][4];
#pragma unroll
    for (int mi = 0; mi < 4; mi++)
#pragma unroll
        for (int ni = 0; ni < 4; ni++)
#pragma unroll
            for (int q = 0; q < 4; q++) c[mi][ni][q] = 0.f;

    const unsigned* uF = (const unsigned*)sF;
    const unsigned* uW = (const unsigned*)sW;

#pragma unroll
    for (int ks = 0; ks < 16; ks++) {
        int k0 = ks * 8;
        unsigned a[4][4], b[4][2];
#pragma unroll
        for (int mi = 0; mi < 4; mi++) {
            int r = wm + mi * 16 + gid;
            a[mi][0] = uF[r * SF + k0 + tig];
            a[mi][1] = uF[(r + 8) * SF + k0 + tig];
            a[mi][2] = uF[r * SF + k0 + tig + 4];
            a[mi][3] = uF[(r + 8) * SF + k0 + tig + 4];
        }
#pragma unroll
        for (int ni = 0; ni < 4; ni++) {
            int cb = wn + ni * 8 + gid;
            b[ni][0] = uW[(k0 + tig) * SW + cb];
            b[ni][1] = uW[(k0 + tig + 4) * SW + cb];
        }
#pragma unroll
        for (int mi = 0; mi < 4; mi++)
#pragma unroll
            for (int ni = 0; ni < 4; ni++)
                asm volatile(
                    "mma.sync.aligned.m16n8k8.row.col.f32.tf32.tf32.f32 "
                    "{%0,%1,%2,%3}, {%4,%5,%6,%7}, {%8,%9}, {%0,%1,%2,%3};"
                    : "+f"(c[mi][ni][0]), "+f"(c[mi][ni][1]),
                      "+f"(c[mi][ni][2]), "+f"(c[mi][ni][3])
                    : "r"(a[mi][0]), "r"(a[mi][1]), "r"(a[mi][2]), "r"(a[mi][3]),
                      "r"(b[ni][0]), "r"(b[ni][1]));
    }

    if (by) {
#pragma unroll
        for (int mi = 0; mi < 4; mi++) {
            int row = node0 + wm + mi * 16 + gid;
#pragma unroll
            for (int ni = 0; ni < 4; ni++) {
                int col = wn + ni * 8 + tig * 2;
                if (row < n)
                    *(float2*)&dres[row * 128 + col] =
                        make_float2(c[mi][ni][0], c[mi][ni][1]);
                if (row + 8 < n)
                    *(float2*)&dres[(row + 8) * 128 + col] =
                        make_float2(c[mi][ni][2], c[mi][ni][3]);
            }
        }
    } else {
#pragma unroll
        for (int mi = 0; mi < 4; mi++) {
            int row = node0 + wm + mi * 16 + gid;
#pragma unroll
            for (int ni = 0; ni < 4; ni++) {
                int col = wn + ni * 8 + tig * 2;
                if (row < n) {
                    __half2 hh = __floats2half2_rn(c[mi][ni][0], c[mi][ni][1]);
                    *(__half2*)&g_xh[row * 128 + col] = hh;
                }
                if (row + 8 < n) {
                    __half2 hh = __floats2half2_rn(c[mi][ni][2], c[mi][ni][3]);
                    *(__half2*)&g_xh[(row + 8) * 128 + col] = hh;
                }
            }
        }
        float2 alv[4], arv[4];
#pragma unroll
        for (int ni = 0; ni < 4; ni++) {
            int col = wn + ni * 8 + tig * 2;
            alv[ni] = *(const float2*)&attl[col];
            arv[ni] = *(const float2*)&attr[col];
        }
        int h_lo = wn >> 4;
#pragma unroll
        for (int mi = 0; mi < 4; mi++) {
            int row = node0 + wm + mi * 16 + gid;
            float v[8];
#pragma unroll
            for (int q = 0; q < 8; q++) v[q] = 0.f;
#pragma unroll
            for (int ni = 0; ni < 2; ni++) {
                v[0] += c[mi][ni][0] * alv[ni].x + c[mi][ni][1] * alv[ni].y;
                v[1] += c[mi][ni][0] * arv[ni].x + c[mi][ni][1] * arv[ni].y;
                v[4] += c[mi][ni][2] * alv[ni].x + c[mi][ni][3] * alv[ni].y;
                v[5] += c[mi][ni][2] * arv[ni].x + c[mi][ni][3] * arv[ni].y;
            }
#pragma unroll
            for (int ni = 2; ni < 4; ni++) {
                v[2] += c[mi][ni][0] * alv[ni].x + c[mi][ni][1] * alv[ni].y;
                v[3] += c[mi][ni][0] * arv[ni].x + c[mi][ni][1] * arv[ni].y;
                v[6] += c[mi][ni][2] * alv[ni].x + c[mi][ni][3] * alv[ni].y;
                v[7] += c[mi][ni][2] * arv[ni].x + c[mi][ni][3] * arv[ni].y;
            }
#pragma unroll
            for (int q = 0; q < 8; q++) {
                v[q] += __shfl_xor_sync(0xffffffffu, v[q], 1);
                v[q] += __shfl_xor_sync(0xffffffffu, v[q], 2);
            }
            if (tig == 0) {
                if (row < n) {
                    g_al[row * 8 + h_lo] = v[0];
                    g_ar[row * 8 + h_lo] = v[1];
                    g_al[row * 8 + h_lo + 1] = v[2];
                    g_ar[row * 8 + h_lo + 1] = v[3];
                }
                if (row + 8 < n) {
                    g_al[(row + 8) * 8 + h_lo] = v[4];
                    g_ar[(row + 8) * 8 + h_lo] = v[5];
                    g_al[(row + 8) * 8 + h_lo + 1] = v[6];
                    g_ar[(row + 8) * 8 + h_lo + 1] = v[7];
                }
            }
        }
    }
}

// ---------------- fused softmax + message passing (exact R12 kernel) -----------
// CRITICAL: no global store may precede or sit inside the gather loop — it
// collapses ptxas load batching and costs ~160us (R7-R11). The g_cnt reset is
// an opaque st.global at the VERY END, after the out store (proven fast, R12).
__global__ void k_agg(float* __restrict__ out, int n) {
    int wid = (blockIdx.x * blockDim.x + threadIdx.x) >> 5;
    int lane = threadIdx.x & 31;
    if (wid >= n) return;
    int beg = wid * PAD;
    int end = beg + min(g_cnt[wid], PAD);
    int h = lane >> 2;
    float arn = g_ar[wid * 8 + h];

    float denom = 0.f;
    float a0 = 0.f, a1 = 0.f, a2 = 0.f, a3 = 0.f;

    int e = beg;
    for (; e + 8 <= end; e += 8) {
        int2 c[8];
#pragma unroll
        for (int j = 0; j < 8; j++) c[j] = g_cs[e + j];
        float l[8];
#pragma unroll
        for (int j = 0; j < 8; j++) l[j] = g_al[c[j].x * 8 + h];
        uint2 x[8];
#pragma unroll
        for (int j = 0; j < 8; j++) x[j] = *(const uint2*)&g_xh[c[j].x * 128 + lane * 4];
#pragma unroll
        for (int j = 0; j < 8; j++) {
            float aa = (l[j] + arn) * __int_as_float(c[j].y);
            aa = (aa > 0.f) ? aa : 0.2f * aa;
            float p = __expf(fminf(aa, 80.f));
            denom += p;
            float2 f0 = __half22float2(*(__half2*)&x[j].x);
            float2 f1 = __half22float2(*(__half2*)&x[j].y);
            a0 += p * f0.x; a1 += p * f0.y; a2 += p * f1.x; a3 += p * f1.y;
        }
    }
    for (; e + 4 <= end; e += 4) {
        int2 c[4];
#pragma unroll
        for (int j = 0; j < 4; j++) c[j] = g_cs[e + j];
        float l[4];
#pragma unroll
        for (int j = 0; j < 4; j++) l[j] = g_al[c[j].x * 8 + h];
        uint2 x[4];
#pragma unroll
        for (int j = 0; j < 4; j++) x[j] = *(const uint2*)&g_xh[c[j].x * 128 + lane * 4];
#pragma unroll
        for (int j = 0; j < 4; j++) {
            float aa = (l[j] + arn) * __int_as_float(c[j].y);
            aa = (aa > 0.f) ? aa : 0.2f * aa;
            float p = __expf(fminf(aa, 80.f));
            denom += p;
            float2 f0 = __half22float2(*(__half2*)&x[j].x);
            float2 f1 = __half22float2(*(__half2*)&x[j].y);
            a0 += p * f0.x; a1 += p * f0.y; a2 += p * f1.x; a3 += p * f1.y;
        }
    }
    for (; e < end; e++) {
        int2 cc = g_cs[e];
        float ll = g_al[cc.x * 8 + h];
        uint2 xx = *(const uint2*)&g_xh[cc.x * 128 + lane * 4];
        float aa = (ll + arn) * __int_as_float(cc.y);
        aa = (aa > 0.f) ? aa : 0.2f * aa;
        float p = __expf(fminf(aa, 80.f));
        denom += p;
        float2 f0 = __half22float2(*(__half2*)&xx.x);
        float2 f1 = __half22float2(*(__half2*)&xx.y);
        a0 += p * f0.x; a1 += p * f0.y; a2 += p * f1.x; a3 += p * f1.y;
    }

    float inv = (end > beg) ? (1.f / denom) : 0.f;
    float fx = a0 * inv, fy = a1 * inv, fz = a2 * inv, fw = a3 * inv;
    fx = (fx > 0.f) ? fx : (__expf(fx) - 1.f);
    fy = (fy > 0.f) ? fy : (__expf(fy) - 1.f);
    fz = (fz > 0.f) ? fz : (__expf(fz) - 1.f);
    fw = (fw > 0.f) ? fw : (__expf(fw) - 1.f);

    float4 r = *(const float4*)&out[wid * 128 + lane * 4];
    r.x += fx; r.y += fy; r.z += fz; r.w += fw;
    *(float4*)&out[wid * 128 + lane * 4] = r;

    // terminal counter reset (replaces k_zero); opaque, program-order-last
    if (lane == 0)
        asm volatile("st.global.b32 [%0], %1;" :: "l"(&g_cnt[wid]), "r"(0));
}

// ---------------- launch ------------------------------------------------------
extern "C" void kernel_launch(void* const* d_in, const int* in_sizes, int n_in,
                              void* d_out, int out_size) {
    const float* feature = (const float*)d_in[0];
    const int*   esrc    = (const int*)d_in[1];
    const int*   edst    = (const int*)d_in[2];
    const float* ew      = (const float*)d_in[3];
    const float* wlin    = (const float*)d_in[4];
    const float* attl    = (const float*)d_in[5];
    const float* attr    = (const float*)d_in[6];
    const float* wres    = (const float*)d_in[7];
    int n = in_sizes[0] / 128;
    int e = in_sizes[1];
    float* out = (float*)d_out;

    cudaFuncSetAttribute(k_fused, cudaFuncAttributeMaxDynamicSharedMemorySize,
                         GEMM_SMEM_BYTES);

    int gb = ((n + 127) / 128) * 2;
    int e4 = (e + 3) / 4;
    int sb = (e4 + 255) / 256;
    k_fused<<<gb + sb, 256, GEMM_SMEM_BYTES>>>(feature, wlin, wres, attl, attr,
                                               out, esrc, edst, ew, n, e, gb);

    k_agg<<<(n * 32 + 255) / 256, 256>>>(out, n);
}

// round 14
// speedup vs baseline: 1.0871x; 1.0871x over previous
#include <cuda_runtime.h>
#include <cuda_fp16.h>

#define NN 50000
#define NE 1600000
#define PAD 128
#define L2E 1.4426950408889634f

// ---------------- scratch (device globals; zero-initialized at load) ----------
__device__ __align__(16) __half g_xh[NN * 128];
__device__ float g_al[NN * 8];
__device__ float g_ar[NN * 8];
__device__ int   g_cnt[NN];          // zeroed at load; reset at TAIL of k_agg
__device__ __align__(16) int2 g_cs[NN * PAD];   // (src, w*log2e bits)

// ---------------- fused: tf32 GEMM (+al/ar epilogue)  ||  edge scatter ---------
#define SF 132
#define SW 136
#define GEMM_SMEM_BYTES ((128 * SF + 128 * SW) * 4)

__device__ __forceinline__ unsigned f2tf32(float f) {
    unsigned u;
    asm("cvt.rna.tf32.f32 %0, %1;" : "=r"(u) : "f"(f));
    return u;
}

__global__ void __launch_bounds__(256) k_fused(
    const float* __restrict__ feat, const float* __restrict__ Wlin,
    const float* __restrict__ Wres, const float* __restrict__ attl,
    const float* __restrict__ attr, float* __restrict__ dres,
    const int* __restrict__ esrc, const int* __restrict__ edst,
    const float* __restrict__ ew, int n, int e, int gb) {

    if ((int)blockIdx.x >= gb) {
        // ================= scatter role =================
        int sbid = blockIdx.x - gb;
        int i0 = (sbid * 256 + threadIdx.x) * 4;
        if (i0 + 4 <= e) {
            int4   s4 = *(const int4*)&esrc[i0];
            int4   d4 = *(const int4*)&edst[i0];
            float4 w4 = *(const float4*)&ew[i0];
            w4.x *= L2E; w4.y *= L2E; w4.z *= L2E; w4.w *= L2E;
            int p0 = atomicAdd(&g_cnt[d4.x], 1);
            int p1 = atomicAdd(&g_cnt[d4.y], 1);
            int p2 = atomicAdd(&g_cnt[d4.z], 1);
            int p3 = atomicAdd(&g_cnt[d4.w], 1);
            p0 = min(p0, PAD - 1); p1 = min(p1, PAD - 1);
            p2 = min(p2, PAD - 1); p3 = min(p3, PAD - 1);
            g_cs[d4.x * PAD + p0] = make_int2(s4.x, __float_as_int(w4.x));
            g_cs[d4.y * PAD + p1] = make_int2(s4.y, __float_as_int(w4.y));
            g_cs[d4.z * PAD + p2] = make_int2(s4.z, __float_as_int(w4.z));
            g_cs[d4.w * PAD + p3] = make_int2(s4.w, __float_as_int(w4.w));
        } else {
            for (int i = i0; i < e; i++) {
                int d = edst[i];
                int p = min(atomicAdd(&g_cnt[d], 1), PAD - 1);
                g_cs[d * PAD + p] = make_int2(esrc[i], __float_as_int(ew[i] * L2E));
            }
        }
        return;
    }

    // ================= GEMM role =================
    int bx = blockIdx.x >> 1;
    int by = blockIdx.x & 1;          // 0 -> x/g_xh (+al/ar), 1 -> residual
    extern __shared__ float sm[];
    float* sF = sm;
    float* sW = sm + 128 * SF;
    int tid = threadIdx.x;
    const float* W = by ? Wres : Wlin;
    int node0 = bx * 128;

#pragma unroll
    for (int t = 0; t < 16; t++) {
        int i = tid + t * 256;
        int r = i >> 5;
        int c4 = i & 31;
        float4 v = ((const float4*)W)[i];
        uint4 u = make_uint4(f2tf32(v.x), f2tf32(v.y), f2tf32(v.z), f2tf32(v.w));
        *(uint4*)&sW[r * SW + c4 * 4] = u;
    }
#pragma unroll
    for (int t = 0; t < 16; t++) {
        int i = tid + t * 256;
        int r = i >> 5;
        int c4 = i & 31;
        int gn = node0 + r;
        float4 v = make_float4(0.f, 0.f, 0.f, 0.f);
        if (gn < n) v = ((const float4*)feat)[gn * 32 + c4];
        uint4 u = make_uint4(f2tf32(v.x), f2tf32(v.y), f2tf32(v.z), f2tf32(v.w));
        *(uint4*)&sF[r * SF + c4 * 4] = u;
    }
    __syncthreads();

    int w = tid >> 5, lane = tid & 31;
    int wm = (w >> 2) * 64;
    int wn = (w & 3) * 32;
    int gid = lane >> 2, tig = lane & 3;

    float c[4][4][4];
#pragma unroll
    for (int mi = 0; mi < 4; mi++)
#pragma unroll
        for (int ni = 0; ni < 4; ni++)
#pragma unroll
            for (int q = 0; q < 4; q++) c[mi][ni][q] = 0.f;

    const unsigned* uF = (const unsigned*)sF;
    const unsigned* uW = (const unsigned*)sW;

#pragma unroll
    for (int ks = 0; ks < 16; ks++) {
        int k0 = ks * 8;
        unsigned a[4][4], b[4][2];
#pragma unroll
        for (int mi = 0; mi < 4; mi++) {
            int r = wm + mi * 16 + gid;
            a[mi][0] = uF[r * SF + k0 + tig];
            a[mi][1] = uF[(r + 8) * SF + k0 + tig];
            a[mi][2] = uF[r * SF + k0 + tig + 4];
            a[mi][3] = uF[(r + 8) * SF + k0 + tig + 4];
        }
#pragma unroll
        for (int ni = 0; ni < 4; ni++) {
            int cb = wn + ni * 8 + gid;
            b[ni][0] = uW[(k0 + tig) * SW + cb];
            b[ni][1] = uW[(k0 + tig + 4) * SW + cb];
        }
#pragma unroll
        for (int mi = 0; mi < 4; mi++)
#pragma unroll
            for (int ni = 0; ni < 4; ni++)
                asm volatile(
                    "mma.sync.aligned.m16n8k8.row.col.f32.tf32.tf32.f32 "
                    "{%0,%1,%2,%3}, {%4,%5,%6,%7}, {%8,%9}, {%0,%1,%2,%3};"
                    : "+f"(c[mi][ni][0]), "+f"(c[mi][ni][1]),
                      "+f"(c[mi][ni][2]), "+f"(c[mi][ni][3])
                    : "r"(a[mi][0]), "r"(a[mi][1]), "r"(a[mi][2]), "r"(a[mi][3]),
                      "r"(b[ni][0]), "r"(b[ni][1]));
    }

    if (by) {
#pragma unroll
        for (int mi = 0; mi < 4; mi++) {
            int row = node0 + wm + mi * 16 + gid;
#pragma unroll
            for (int ni = 0; ni < 4; ni++) {
                int col = wn + ni * 8 + tig * 2;
                if (row < n)
                    *(float2*)&dres[row * 128 + col] =
                        make_float2(c[mi][ni][0], c[mi][ni][1]);
                if (row + 8 < n)
                    *(float2*)&dres[(row + 8) * 128 + col] =
                        make_float2(c[mi][ni][2], c[mi][ni][3]);
            }
        }
    } else {
#pragma unroll
        for (int mi = 0; mi < 4; mi++) {
            int row = node0 + wm + mi * 16 + gid;
#pragma unroll
            for (int ni = 0; ni < 4; ni++) {
                int col = wn + ni * 8 + tig * 2;
                if (row < n) {
                    __half2 hh = __floats2half2_rn(c[mi][ni][0], c[mi][ni][1]);
                    *(__half2*)&g_xh[row * 128 + col] = hh;
                }
                if (row + 8 < n) {
                    __half2 hh = __floats2half2_rn(c[mi][ni][2], c[mi][ni][3]);
                    *(__half2*)&g_xh[(row + 8) * 128 + col] = hh;
                }
            }
        }
        float2 alv[4], arv[4];
#pragma unroll
        for (int ni = 0; ni < 4; ni++) {
            int col = wn + ni * 8 + tig * 2;
            alv[ni] = *(const float2*)&attl[col];
            arv[ni] = *(const float2*)&attr[col];
        }
        int h_lo = wn >> 4;
#pragma unroll
        for (int mi = 0; mi < 4; mi++) {
            int row = node0 + wm + mi * 16 + gid;
            float v[8];
#pragma unroll
            for (int q = 0; q < 8; q++) v[q] = 0.f;
#pragma unroll
            for (int ni = 0; ni < 2; ni++) {
                v[0] += c[mi][ni][0] * alv[ni].x + c[mi][ni][1] * alv[ni].y;
                v[1] += c[mi][ni][0] * arv[ni].x + c[mi][ni][1] * arv[ni].y;
                v[4] += c[mi][ni][2] * alv[ni].x + c[mi][ni][3] * alv[ni].y;
                v[5] += c[mi][ni][2] * arv[ni].x + c[mi][ni][3] * arv[ni].y;
            }
#pragma unroll
            for (int ni = 2; ni < 4; ni++) {
                v[2] += c[mi][ni][0] * alv[ni].x + c[mi][ni][1] * alv[ni].y;
                v[3] += c[mi][ni][0] * arv[ni].x + c[mi][ni][1] * arv[ni].y;
                v[6] += c[mi][ni][2] * alv[ni].x + c[mi][ni][3] * alv[ni].y;
                v[7] += c[mi][ni][2] * arv[ni].x + c[mi][ni][3] * arv[ni].y;
            }
#pragma unroll
            for (int q = 0; q < 8; q++) {
                v[q] += __shfl_xor_sync(0xffffffffu, v[q], 1);
                v[q] += __shfl_xor_sync(0xffffffffu, v[q], 2);
            }
            if (tig == 0) {
                if (row < n) {
                    g_al[row * 8 + h_lo] = v[0];
                    g_ar[row * 8 + h_lo] = v[1];
                    g_al[row * 8 + h_lo + 1] = v[2];
                    g_ar[row * 8 + h_lo + 1] = v[3];
                }
                if (row + 8 < n) {
                    g_al[(row + 8) * 8 + h_lo] = v[4];
                    g_ar[(row + 8) * 8 + h_lo] = v[5];
                    g_al[(row + 8) * 8 + h_lo + 1] = v[6];
                    g_ar[(row + 8) * 8 + h_lo + 1] = v[7];
                }
            }
        }
    }
}

// ---------------- fused softmax + message passing, half-warp per edge ----------
// lane = (hl = lane>>4: which edge of a pair, li = lane&15: column group).
// Each lane loads uint4 (8 cols) so 16 lanes cover the row; the warp processes
// TWO edges per step. Halves are combined with shfl_xor(16) AFTER the loop.
// CRITICAL: no global store before/inside the gather loop (R7-R11 lesson);
// g_cnt reset is an opaque terminal st.global (R12-proven).
__global__ void k_agg(float* __restrict__ out, int n) {
    int wid = (blockIdx.x * blockDim.x + threadIdx.x) >> 5;
    int lane = threadIdx.x & 31;
    if (wid >= n) return;
    int cnt0 = min(g_cnt[wid], PAD);
    int beg = wid * PAD;
    int end = beg + cnt0;

    int li = lane & 15;          // column group: cols [8*li, 8*li+8)
    int hl = lane >> 4;          // edge-of-pair id
    int head = li >> 1;
    float arn = g_ar[wid * 8 + head];

    float denom = 0.f;
    float a[8];
#pragma unroll
    for (int k = 0; k < 8; k++) a[k] = 0.f;

    int e = beg;
    // main: 8 pairs = 16 edges
    for (; e + 16 <= end; e += 16) {
        int2 c[8];
#pragma unroll
        for (int j = 0; j < 8; j++) c[j] = g_cs[e + 2 * j + hl];
        float l[8];
#pragma unroll
        for (int j = 0; j < 8; j++) l[j] = g_al[c[j].x * 8 + head];
        uint4 x[8];
#pragma unroll
        for (int j = 0; j < 8; j++) x[j] = *(const uint4*)&g_xh[c[j].x * 128 + li * 8];
#pragma unroll
        for (int j = 0; j < 8; j++) {
            float aa = (l[j] + arn) * __int_as_float(c[j].y);
            aa = (aa > 0.f) ? aa : 0.2f * aa;
            float p = exp2f(fminf(aa, 100.f));
            denom += p;
            float2 f0 = __half22float2(*(__half2*)&x[j].x);
            float2 f1 = __half22float2(*(__half2*)&x[j].y);
            float2 f2 = __half22float2(*(__half2*)&x[j].z);
            float2 f3 = __half22float2(*(__half2*)&x[j].w);
            a[0] += p * f0.x; a[1] += p * f0.y; a[2] += p * f1.x; a[3] += p * f1.y;
            a[4] += p * f2.x; a[5] += p * f2.y; a[6] += p * f3.x; a[7] += p * f3.y;
        }
    }
    // 4 pairs = 8 edges
    for (; e + 8 <= end; e += 8) {
        int2 c[4];
#pragma unroll
        for (int j = 0; j < 4; j++) c[j] = g_cs[e + 2 * j + hl];
        float l[4];
#pragma unroll
        for (int j = 0; j < 4; j++) l[j] = g_al[c[j].x * 8 + head];
        uint4 x[4];
#pragma unroll
        for (int j = 0; j < 4; j++) x[j] = *(const uint4*)&g_xh[c[j].x * 128 + li * 8];
#pragma unroll
        for (int j = 0; j < 4; j++) {
            float aa = (l[j] + arn) * __int_as_float(c[j].y);
            aa = (aa > 0.f) ? aa : 0.2f * aa;
            float p = exp2f(fminf(aa, 100.f));
            denom += p;
            float2 f0 = __half22float2(*(__half2*)&x[j].x);
            float2 f1 = __half22float2(*(__half2*)&x[j].y);
            float2 f2 = __half22float2(*(__half2*)&x[j].z);
            float2 f3 = __half22float2(*(__half2*)&x[j].w);
            a[0] += p * f0.x; a[1] += p * f0.y; a[2] += p * f1.x; a[3] += p * f1.y;
            a[4] += p * f2.x; a[5] += p * f2.y; a[6] += p * f3.x; a[7] += p * f3.y;
        }
    }
    // single pairs = 2 edges
    for (; e + 2 <= end; e += 2) {
        int2 cc = g_cs[e + hl];
        float ll = g_al[cc.x * 8 + head];
        uint4 xx = *(const uint4*)&g_xh[cc.x * 128 + li * 8];
        float aa = (ll + arn) * __int_as_float(cc.y);
        aa = (aa > 0.f) ? aa : 0.2f * aa;
        float p = exp2f(fminf(aa, 100.f));
        denom += p;
        float2 f0 = __half22float2(*(__half2*)&xx.x);
        float2 f1 = __half22float2(*(__half2*)&xx.y);
        float2 f2 = __half22float2(*(__half2*)&xx.z);
        float2 f3 = __half22float2(*(__half2*)&xx.w);
        a[0] += p * f0.x; a[1] += p * f0.y; a[2] += p * f1.x; a[3] += p * f1.y;
        a[4] += p * f2.x; a[5] += p * f2.y; a[6] += p * f3.x; a[7] += p * f3.y;
    }
    // odd leftover edge: both halves see it; zero p for hl==1
    if (e < end) {
        int2 cc = g_cs[e];
        float ll = g_al[cc.x * 8 + head];
        uint4 xx = *(const uint4*)&g_xh[cc.x * 128 + li * 8];
        float aa = (ll + arn) * __int_as_float(cc.y);
        aa = (aa > 0.f) ? aa : 0.2f * aa;
        float p = exp2f(fminf(aa, 100.f));
        if (hl) p = 0.f;
        denom += p;
        float2 f0 = __half22float2(*(__half2*)&xx.x);
        float2 f1 = __half22float2(*(__half2*)&xx.y);
        float2 f2 = __half22float2(*(__half2*)&xx.z);
        float2 f3 = __half22float2(*(__half2*)&xx.w);
        a[0] += p * f0.x; a[1] += p * f0.y; a[2] += p * f1.x; a[3] += p * f1.y;
        a[4] += p * f2.x; a[5] += p * f2.y; a[6] += p * f3.x; a[7] += p * f3.y;
    }

    // combine the two halves (post-loop shuffles only)
    denom += __shfl_xor_sync(0xffffffffu, denom, 16);
#pragma unroll
    for (int k = 0; k < 8; k++) a[k] += __shfl_xor_sync(0xffffffffu, a[k], 16);

    if (hl == 0) {
        float inv = (cnt0 > 0) ? (1.f / denom) : 0.f;
        float f[8];
#pragma unroll
        for (int k = 0; k < 8; k++) {
            float v = a[k] * inv;
            f[k] = (v > 0.f) ? v : (__expf(v) - 1.f);
        }
        float4 r0 = *(const float4*)&out[wid * 128 + li * 8];
        float4 r1 = *(const float4*)&out[wid * 128 + li * 8 + 4];
        r0.x += f[0]; r0.y += f[1]; r0.z += f[2]; r0.w += f[3];
        r1.x += f[4]; r1.y += f[5]; r1.z += f[6]; r1.w += f[7];
        *(float4*)&out[wid * 128 + li * 8] = r0;
        *(float4*)&out[wid * 128 + li * 8 + 4] = r1;
    }

    // terminal counter reset (replaces k_zero); opaque, program-order-last
    if (lane == 0)
        asm volatile("st.global.b32 [%0], %1;" :: "l"(&g_cnt[wid]), "r"(0));
}

// ---------------- launch ------------------------------------------------------
extern "C" void kernel_launch(void* const* d_in, const int* in_sizes, int n_in,
                              void* d_out, int out_size) {
    const float* feature = (const float*)d_in[0];
    const int*   esrc    = (const int*)d_in[1];
    const int*   edst    = (const int*)d_in[2];
    const float* ew      = (const float*)d_in[3];
    const float* wlin    = (const float*)d_in[4];
    const float* attl    = (const float*)d_in[5];
    const float* attr    = (const float*)d_in[6];
    const float* wres    = (const float*)d_in[7];
    int n = in_sizes[0] / 128;
    int e = in_sizes[1];
    float* out = (float*)d_out;

    cudaFuncSetAttribute(k_fused, cudaFuncAttributeMaxDynamicSharedMemorySize,
                         GEMM_SMEM_BYTES);

    int gb = ((n + 127) / 128) * 2;
    int e4 = (e + 3) / 4;
    int sb = (e4 + 255) / 256;
    k_fused<<<gb + sb, 256, GEMM_SMEM_BYTES>>>(feature, wlin, wres, attl, attr,
                                               out, esrc, edst, ew, n, e, gb);

    k_agg<<<(n * 32 + 255) / 256, 256>>>(out, n);
}

// round 15
// speedup vs baseline: 1.0912x; 1.0038x over previous
#include <cuda_runtime.h>
#include <cuda_fp16.h>

#define NN 50000
#define NE 1600000
#define PAD 128
#define L2E 1.4426950408889634f

// ---------------- scratch (device globals; zero-initialized at load) ----------
__device__ __align__(16) __half g_xh[NN * 128];
__device__ float g_al[NN * 8];
__device__ float g_ar[NN * 8];
__device__ int   g_cnt[NN];          // zeroed at load; reset at TAIL of k_agg
__device__ __align__(16) int2 g_cs[NN * PAD];   // (src, w*log2e bits)

// ---------------- fused: tf32 GEMM (+al/ar epilogue)  ||  edge scatter ---------
#define SF 132
#define SW 136
#define GEMM_SMEM_BYTES ((128 * SF + 128 * SW) * 4)

__device__ __forceinline__ unsigned f2tf32(float f) {
    unsigned u;
    asm("cvt.rna.tf32.f32 %0, %1;" : "=r"(u) : "f"(f));
    return u;
}

__global__ void __launch_bounds__(256) k_fused(
    const float* __restrict__ feat, const float* __restrict__ Wlin,
    const float* __restrict__ Wres, const float* __restrict__ attl,
    const float* __restrict__ attr, float* __restrict__ dres,
    const int* __restrict__ esrc, const int* __restrict__ edst,
    const float* __restrict__ ew, int n, int e, int gb) {

    if ((int)blockIdx.x >= gb) {
        // ================= scatter role =================
        int sbid = blockIdx.x - gb;
        int i0 = (sbid * 256 + threadIdx.x) * 4;
        if (i0 + 4 <= e) {
            int4   s4 = *(const int4*)&esrc[i0];
            int4   d4 = *(const int4*)&edst[i0];
            float4 w4 = *(const float4*)&ew[i0];
            w4.x *= L2E; w4.y *= L2E; w4.z *= L2E; w4.w *= L2E;
            int p0 = atomicAdd(&g_cnt[d4.x], 1);
            int p1 = atomicAdd(&g_cnt[d4.y], 1);
            int p2 = atomicAdd(&g_cnt[d4.z], 1);
            int p3 = atomicAdd(&g_cnt[d4.w], 1);
            p0 = min(p0, PAD - 1); p1 = min(p1, PAD - 1);
            p2 = min(p2, PAD - 1); p3 = min(p3, PAD - 1);
            g_cs[d4.x * PAD + p0] = make_int2(s4.x, __float_as_int(w4.x));
            g_cs[d4.y * PAD + p1] = make_int2(s4.y, __float_as_int(w4.y));
            g_cs[d4.z * PAD + p2] = make_int2(s4.z, __float_as_int(w4.z));
            g_cs[d4.w * PAD + p3] = make_int2(s4.w, __float_as_int(w4.w));
        } else {
            for (int i = i0; i < e; i++) {
                int d = edst[i];
                int p = min(atomicAdd(&g_cnt[d], 1), PAD - 1);
                g_cs[d * PAD + p] = make_int2(esrc[i], __float_as_int(ew[i] * L2E));
            }
        }
        return;
    }

    // ================= GEMM role =================
    int bx = blockIdx.x >> 1;
    int by = blockIdx.x & 1;          // 0 -> x/g_xh (+al/ar), 1 -> residual
    extern __shared__ float sm[];
    float* sF = sm;
    float* sW = sm + 128 * SF;
    int tid = threadIdx.x;
    const float* W = by ? Wres : Wlin;
    int node0 = bx * 128;

#pragma unroll
    for (int t = 0; t < 16; t++) {
        int i = tid + t * 256;
        int r = i >> 5;
        int c4 = i & 31;
        float4 v = ((const float4*)W)[i];
        uint4 u = make_uint4(f2tf32(v.x), f2tf32(v.y), f2tf32(v.z), f2tf32(v.w));
        *(uint4*)&sW[r * SW + c4 * 4] = u;
    }
#pragma unroll
    for (int t = 0; t < 16; t++) {
        int i = tid + t * 256;
        int r = i >> 5;
        int c4 = i & 31;
        int gn = node0 + r;
        float4 v = make_float4(0.f, 0.f, 0.f, 0.f);
        if (gn < n) v = ((const float4*)feat)[gn * 32 + c4];
        uint4 u = make_uint4(f2tf32(v.x), f2tf32(v.y), f2tf32(v.z), f2tf32(v.w));
        *(uint4*)&sF[r * SF + c4 * 4] = u;
    }
    __syncthreads();

    int w = tid >> 5, lane = tid & 31;
    int wm = (w >> 2) * 64;
    int wn = (w & 3) * 32;
    int gid = lane >> 2, tig = lane & 3;

    float c[4][4][4];
#pragma unroll
    for (int mi = 0; mi < 4; mi++)
#pragma unroll
        for (int ni = 0; ni < 4; ni++)
#pragma unroll
            for (int q = 0; q < 4; q++) c[mi][ni][q] = 0.f;

    const unsigned* uF = (const unsigned*)sF;
    const unsigned* uW = (const unsigned*)sW;

#pragma unroll
    for (int ks = 0; ks < 16; ks++) {
        int k0 = ks * 8;
        unsigned a[4][4], b[4][2];
#pragma unroll
        for (int mi = 0; mi < 4; mi++) {
            int r = wm + mi * 16 + gid;
            a[mi][0] = uF[r * SF + k0 + tig];
            a[mi][1] = uF[(r + 8) * SF + k0 + tig];
            a[mi][2] = uF[r * SF + k0 + tig + 4];
            a[mi][3] = uF[(r + 8) * SF + k0 + tig + 4];
        }
#pragma unroll
        for (int ni = 0; ni < 4; ni++) {
            int cb = wn + ni * 8 + gid;
            b[ni][0] = uW[(k0 + tig) * SW + cb];
            b[ni][1] = uW[(k0 + tig + 4) * SW + cb];
        }
#pragma unroll
        for (int mi = 0; mi < 4; mi++)
#pragma unroll
            for (int ni = 0; ni < 4; ni++)
                asm volatile(
                    "mma.sync.aligned.m16n8k8.row.col.f32.tf32.tf32.f32 "
                    "{%0,%1,%2,%3}, {%4,%5,%6,%7}, {%8,%9}, {%0,%1,%2,%3};"
                    : "+f"(c[mi][ni][0]), "+f"(c[mi][ni][1]),
                      "+f"(c[mi][ni][2]), "+f"(c[mi][ni][3])
                    : "r"(a[mi][0]), "r"(a[mi][1]), "r"(a[mi][2]), "r"(a[mi][3]),
                      "r"(b[ni][0]), "r"(b[ni][1]));
    }

    if (by) {
#pragma unroll
        for (int mi = 0; mi < 4; mi++) {
            int row = node0 + wm + mi * 16 + gid;
#pragma unroll
            for (int ni = 0; ni < 4; ni++) {
                int col = wn + ni * 8 + tig * 2;
                if (row < n)
                    *(float2*)&dres[row * 128 + col] =
                        make_float2(c[mi][ni][0], c[mi][ni][1]);
                if (row + 8 < n)
                    *(float2*)&dres[(row + 8) * 128 + col] =
                        make_float2(c[mi][ni][2], c[mi][ni][3]);
            }
        }
    } else {
#pragma unroll
        for (int mi = 0; mi < 4; mi++) {
            int row = node0 + wm + mi * 16 + gid;
#pragma unroll
            for (int ni = 0; ni < 4; ni++) {
                int col = wn + ni * 8 + tig * 2;
                if (row < n) {
                    __half2 hh = __floats2half2_rn(c[mi][ni][0], c[mi][ni][1]);
                    *(__half2*)&g_xh[row * 128 + col] = hh;
                }
                if (row + 8 < n) {
                    __half2 hh = __floats2half2_rn(c[mi][ni][2], c[mi][ni][3]);
                    *(__half2*)&g_xh[(row + 8) * 128 + col] = hh;
                }
            }
        }
        float2 alv[4], arv[4];
#pragma unroll
        for (int ni = 0; ni < 4; ni++) {
            int col = wn + ni * 8 + tig * 2;
            alv[ni] = *(const float2*)&attl[col];
            arv[ni] = *(const float2*)&attr[col];
        }
        int h_lo = wn >> 4;
#pragma unroll
        for (int mi = 0; mi < 4; mi++) {
            int row = node0 + wm + mi * 16 + gid;
            float v[8];
#pragma unroll
            for (int q = 0; q < 8; q++) v[q] = 0.f;
#pragma unroll
            for (int ni = 0; ni < 2; ni++) {
                v[0] += c[mi][ni][0] * alv[ni].x + c[mi][ni][1] * alv[ni].y;
                v[1] += c[mi][ni][0] * arv[ni].x + c[mi][ni][1] * arv[ni].y;
                v[4] += c[mi][ni][2] * alv[ni].x + c[mi][ni][3] * alv[ni].y;
                v[5] += c[mi][ni][2] * arv[ni].x + c[mi][ni][3] * arv[ni].y;
            }
#pragma unroll
            for (int ni = 2; ni < 4; ni++) {
                v[2] += c[mi][ni][0] * alv[ni].x + c[mi][ni][1] * alv[ni].y;
                v[3] += c[mi][ni][0] * arv[ni].x + c[mi][ni][1] * arv[ni].y;
                v[6] += c[mi][ni][2] * alv[ni].x + c[mi][ni][3] * alv[ni].y;
                v[7] += c[mi][ni][2] * arv[ni].x + c[mi][ni][3] * arv[ni].y;
            }
#pragma unroll
            for (int q = 0; q < 8; q++) {
                v[q] += __shfl_xor_sync(0xffffffffu, v[q], 1);
                v[q] += __shfl_xor_sync(0xffffffffu, v[q], 2);
            }
            if (tig == 0) {
                if (row < n) {
                    g_al[row * 8 + h_lo] = v[0];
                    g_ar[row * 8 + h_lo] = v[1];
                    g_al[row * 8 + h_lo + 1] = v[2];
                    g_ar[row * 8 + h_lo + 1] = v[3];
                }
                if (row + 8 < n) {
                    g_al[(row + 8) * 8 + h_lo] = v[4];
                    g_ar[(row + 8) * 8 + h_lo] = v[5];
                    g_al[(row + 8) * 8 + h_lo + 1] = v[6];
                    g_ar[(row + 8) * 8 + h_lo + 1] = v[7];
                }
            }
        }
    }
}

// ---------------- fused softmax + message passing, quarter-warp per edge -------
// lane = (ql = lane>>3: edge-of-quad, li = lane&7: head / 16-col group).
// Each lane owns exactly head li, cols [16li,16li+16) via two uint4 loads.
// Warp processes FOUR edges per step; halves combined post-loop via
// shfl_xor(8) + shfl_xor(16). Same discipline as R14: arrays-then-compute,
// no stores/shuffles inside the gather loop; terminal-only g_cnt reset.
__global__ void k_agg(float* __restrict__ out, int n) {
    int wid = (blockIdx.x * blockDim.x + threadIdx.x) >> 5;
    int lane = threadIdx.x & 31;
    if (wid >= n) return;
    int cnt0 = min(g_cnt[wid], PAD);
    int beg = wid * PAD;
    int end = beg + cnt0;

    int li = lane & 7;           // head id AND column group [16li, 16li+16)
    int ql = lane >> 3;          // edge-of-quad id
    float arn = g_ar[wid * 8 + li];

    float denom = 0.f;
    float a[16];
#pragma unroll
    for (int k = 0; k < 16; k++) a[k] = 0.f;

    int e = beg;
    // main: 2 quads = 8 edges
    for (; e + 8 <= end; e += 8) {
        int2 c[2];
#pragma unroll
        for (int j = 0; j < 2; j++) c[j] = g_cs[e + 4 * j + ql];
        float l[2];
#pragma unroll
        for (int j = 0; j < 2; j++) l[j] = g_al[c[j].x * 8 + li];
        uint4 x0[2], x1[2];
#pragma unroll
        for (int j = 0; j < 2; j++) {
            x0[j] = *(const uint4*)&g_xh[c[j].x * 128 + li * 16];
            x1[j] = *(const uint4*)&g_xh[c[j].x * 128 + li * 16 + 8];
        }
#pragma unroll
        for (int j = 0; j < 2; j++) {
            float aa = (l[j] + arn) * __int_as_float(c[j].y);
            aa = (aa > 0.f) ? aa : 0.2f * aa;
            float p = exp2f(fminf(aa, 100.f));
            denom += p;
            float2 f;
            f = __half22float2(*(__half2*)&x0[j].x); a[0] += p * f.x; a[1] += p * f.y;
            f = __half22float2(*(__half2*)&x0[j].y); a[2] += p * f.x; a[3] += p * f.y;
            f = __half22float2(*(__half2*)&x0[j].z); a[4] += p * f.x; a[5] += p * f.y;
            f = __half22float2(*(__half2*)&x0[j].w); a[6] += p * f.x; a[7] += p * f.y;
            f = __half22float2(*(__half2*)&x1[j].x); a[8] += p * f.x; a[9] += p * f.y;
            f = __half22float2(*(__half2*)&x1[j].y); a[10] += p * f.x; a[11] += p * f.y;
            f = __half22float2(*(__half2*)&x1[j].z); a[12] += p * f.x; a[13] += p * f.y;
            f = __half22float2(*(__half2*)&x1[j].w); a[14] += p * f.x; a[15] += p * f.y;
        }
    }
    // one quad = 4 edges
    if (e + 4 <= end) {
        int2 cc = g_cs[e + ql];
        float ll = g_al[cc.x * 8 + li];
        uint4 y0 = *(const uint4*)&g_xh[cc.x * 128 + li * 16];
        uint4 y1 = *(const uint4*)&g_xh[cc.x * 128 + li * 16 + 8];
        float aa = (ll + arn) * __int_as_float(cc.y);
        aa = (aa > 0.f) ? aa : 0.2f * aa;
        float p = exp2f(fminf(aa, 100.f));
        denom += p;
        float2 f;
        f = __half22float2(*(__half2*)&y0.x); a[0] += p * f.x; a[1] += p * f.y;
        f = __half22float2(*(__half2*)&y0.y); a[2] += p * f.x; a[3] += p * f.y;
        f = __half22float2(*(__half2*)&y0.z); a[4] += p * f.x; a[5] += p * f.y;
        f = __half22float2(*(__half2*)&y0.w); a[6] += p * f.x; a[7] += p * f.y;
        f = __half22float2(*(__half2*)&y1.x); a[8] += p * f.x; a[9] += p * f.y;
        f = __half22float2(*(__half2*)&y1.y); a[10] += p * f.x; a[11] += p * f.y;
        f = __half22float2(*(__half2*)&y1.z); a[12] += p * f.x; a[13] += p * f.y;
        f = __half22float2(*(__half2*)&y1.w); a[14] += p * f.x; a[15] += p * f.y;
        e += 4;
    }
    // leftover 1..3 edges: all quads see each edge; only ql==0 contributes
    for (; e < end; e++) {
        int2 cc = g_cs[e];
        float ll = g_al[cc.x * 8 + li];
        uint4 y0 = *(const uint4*)&g_xh[cc.x * 128 + li * 16];
        uint4 y1 = *(const uint4*)&g_xh[cc.x * 128 + li * 16 + 8];
        float aa = (ll + arn) * __int_as_float(cc.y);
        aa = (aa > 0.f) ? aa : 0.2f * aa;
        float p = exp2f(fminf(aa, 100.f));
        if (ql) p = 0.f;
        denom += p;
        float2 f;
        f = __half22float2(*(__half2*)&y0.x); a[0] += p * f.x; a[1] += p * f.y;
        f = __half22float2(*(__half2*)&y0.y); a[2] += p * f.x; a[3] += p * f.y;
        f = __half22float2(*(__half2*)&y0.z); a[4] += p * f.x; a[5] += p * f.y;
        f = __half22float2(*(__half2*)&y0.w); a[6] += p * f.x; a[7] += p * f.y;
        f = __half22float2(*(__half2*)&y1.x); a[8] += p * f.x; a[9] += p * f.y;
        f = __half22float2(*(__half2*)&y1.y); a[10] += p * f.x; a[11] += p * f.y;
        f = __half22float2(*(__half2*)&y1.z); a[12] += p * f.x; a[13] += p * f.y;
        f = __half22float2(*(__half2*)&y1.w); a[14] += p * f.x; a[15] += p * f.y;
    }

    // combine quads (post-loop shuffles only): reduce over ql bits (8, 16)
    denom += __shfl_xor_sync(0xffffffffu, denom, 8);
    denom += __shfl_xor_sync(0xffffffffu, denom, 16);
#pragma unroll
    for (int k = 0; k < 16; k++) {
        a[k] += __shfl_xor_sync(0xffffffffu, a[k], 8);
        a[k] += __shfl_xor_sync(0xffffffffu, a[k], 16);
    }

    if (ql == 0) {
        float inv = (cnt0 > 0) ? (1.f / denom) : 0.f;
        int base = wid * 128 + li * 16;
#pragma unroll
        for (int q = 0; q < 4; q++) {
            float4 r = *(const float4*)&out[base + q * 4];
            float v0 = a[q * 4 + 0] * inv;
            float v1 = a[q * 4 + 1] * inv;
            float v2 = a[q * 4 + 2] * inv;
            float v3 = a[q * 4 + 3] * inv;
            r.x += (v0 > 0.f) ? v0 : (__expf(v0) - 1.f);
            r.y += (v1 > 0.f) ? v1 : (__expf(v1) - 1.f);
            r.z += (v2 > 0.f) ? v2 : (__expf(v2) - 1.f);
            r.w += (v3 > 0.f) ? v3 : (__expf(v3) - 1.f);
            *(float4*)&out[base + q * 4] = r;
        }
    }

    // terminal counter reset (replaces k_zero); opaque, program-order-last
    if (lane == 0)
        asm volatile("st.global.b32 [%0], %1;" :: "l"(&g_cnt[wid]), "r"(0));
}

// ---------------- launch ------------------------------------------------------
extern "C" void kernel_launch(void* const* d_in, const int* in_sizes, int n_in,
                              void* d_out, int out_size) {
    const float* feature = (const float*)d_in[0];
    const int*   esrc    = (const int*)d_in[1];
    const int*   edst    = (const int*)d_in[2];
    const float* ew      = (const float*)d_in[3];
    const float* wlin    = (const float*)d_in[4];
    const float* attl    = (const float*)d_in[5];
    const float* attr    = (const float*)d_in[6];
    const float* wres    = (const float*)d_in[7];
    int n = in_sizes[0] / 128;
    int e = in_sizes[1];
    float* out = (float*)d_out;

    cudaFuncSetAttribute(k_fused, cudaFuncAttributeMaxDynamicSharedMemorySize,
                         GEMM_SMEM_BYTES);

    int gb = ((n + 127) / 128) * 2;
    int e4 = (e + 3) / 4;
    int sb = (e4 + 255) / 256;
    k_fused<<<gb + sb, 256, GEMM_SMEM_BYTES>>>(feature, wlin, wres, attl, attr,
                                               out, esrc, edst, ew, n, e, gb);

    k_agg<<<(n * 32 + 255) / 256, 256>>>(out, n);
}